// round 15
// baseline (speedup 1.0000x reference)
#include <cuda_runtime.h>
#include <cuda_bf16.h>
#include <cuda_fp16.h>
#include <cstdint>

#define NN   50000
#define EE   800000
#define ETOT 850000   // EE + NN self loops
#define MPAD 50048    // 391 * 128
#define FIN  128
#define HID  256
#define OUTC 40
#define NEG  0.2f

// ---------------- device scratch (no cudaMalloc allowed) ----------------
__device__ __align__(16) float g_xr0[(size_t)NN * 256];
__device__ __align__(16) __half g_xl0h[(size_t)NN * 256];   // fp16 xl0 (GEMM epilogue emit)
__device__ __align__(16) float g_asrc0[NN * 4];
__device__ __align__(16) float g_adst0[NN * 4];
__device__ __align__(16) float g_xr1[(size_t)NN * OUTC];
__device__ __align__(16) __half g_xl1h[(size_t)NN * OUTC];
__device__ float g_asrc1[NN];
__device__ float g_adst1[NN];
__device__ int   g_deg[NN];
__device__ int   g_rowstart[NN + 1];
__device__ int   g_cursor[NN];
__device__ int   g_esrc[ETOT];
__device__ int   g_bsums[64];
__device__ int   g_is64;
// pre-split bf16 operand planes (padded, guard-free GEMM loads)
__device__ __align__(16) __nv_bfloat16 g_a0hi[(size_t)MPAD * FIN];
__device__ __align__(16) __nv_bfloat16 g_a0lo[(size_t)MPAD * FIN];
__device__ __align__(16) __nv_bfloat16 g_a1hi[(size_t)MPAD * HID];
__device__ __align__(16) __nv_bfloat16 g_a1lo[(size_t)MPAD * HID];
__device__ __align__(16) __nv_bfloat16 g_bhi[98304];
__device__ __align__(16) __nv_bfloat16 g_blo[98304];

// ---- side stream + events for fork/join inside graph capture -----------
struct SideStream {
    cudaStream_t s2;
    cudaEvent_t evFork, evPack, evJoin;
    SideStream() {
        cudaStreamCreateWithFlags(&s2, cudaStreamNonBlocking);
        cudaEventCreateWithFlags(&evFork, cudaEventDisableTiming);
        cudaEventCreateWithFlags(&evPack, cudaEventDisableTiming);
        cudaEventCreateWithFlags(&evJoin, cudaEventDisableTiming);
    }
};
static SideStream g_ss;

// ======================= PTX helpers ====================================
__device__ __forceinline__ uint32_t smem_u32(const void* p) {
    uint32_t a;
    asm("{ .reg .u64 t; cvta.to.shared.u64 t, %1; cvt.u32.u64 %0, t; }" : "=r"(a) : "l"(p));
    return a;
}
__device__ __forceinline__ void ldsm_x4(uint32_t* r, uint32_t addr) {
    asm volatile("ldmatrix.sync.aligned.m8n8.x4.shared.b16 {%0,%1,%2,%3}, [%4];"
        : "=r"(r[0]), "=r"(r[1]), "=r"(r[2]), "=r"(r[3]) : "r"(addr));
}
__device__ __forceinline__ void ldsm_x2(uint32_t* r, uint32_t addr) {
    asm volatile("ldmatrix.sync.aligned.m8n8.x2.shared.b16 {%0,%1}, [%2];"
        : "=r"(r[0]), "=r"(r[1]) : "r"(addr));
}
__device__ __forceinline__ void mma16816(float* d, const uint32_t* a, const uint32_t* b) {
    asm volatile("mma.sync.aligned.m16n8k16.row.col.f32.bf16.bf16.f32 "
        "{%0,%1,%2,%3}, {%4,%5,%6,%7}, {%8,%9}, {%0,%1,%2,%3};"
        : "+f"(d[0]), "+f"(d[1]), "+f"(d[2]), "+f"(d[3])
        : "r"(a[0]), "r"(a[1]), "r"(a[2]), "r"(a[3]), "r"(b[0]), "r"(b[1]));
}
__device__ __forceinline__ void cp16(uint32_t dst, const void* src) {
    asm volatile("cp.async.cg.shared.global [%0], [%1], 16;" :: "r"(dst), "l"(src));
}
#define CP_COMMIT() asm volatile("cp.async.commit_group;")
#define CP_WAIT1()  asm volatile("cp.async.wait_group 1;")

// ------------- zero degrees + dtype detect (merged, side chain) ---------
__global__ void zero_detect_kernel(const int* __restrict__ ei) {
    int i = blockIdx.x * blockDim.x + threadIdx.x;
    if (i < NN) g_deg[i] = 0;
    if (blockIdx.x == 0 && threadIdx.x < 32) {
        int lane = threadIdx.x;
        int nz = 0;
        for (int k = lane * 2 + 1; k < 256; k += 64) nz += (ei[k] != 0);
        unsigned m = __ballot_sync(0xffffffffu, nz != 0);
        if (lane == 0) g_is64 = (m == 0u) ? 1 : 0;
    }
}

__global__ void hist_kernel(const int* __restrict__ ei) {
    int e = blockIdx.x * blockDim.x + threadIdx.x;
    if (e >= EE) return;
    int d;
    if (g_is64) d = (int)((const long long*)ei)[EE + e];
    else        d = ei[EE + e];
    atomicAdd(&g_deg[d], 1);
}

__global__ void scanA_kernel() {
    __shared__ int sh[1024];
    int i = blockIdx.x * 1024 + threadIdx.x;
    int v = (i < NN) ? (g_deg[i] + 1) : 0;
    sh[threadIdx.x] = v;
    __syncthreads();
    for (int off = 1; off < 1024; off <<= 1) {
        int t = (threadIdx.x >= off) ? sh[threadIdx.x - off] : 0;
        __syncthreads();
        sh[threadIdx.x] += t;
        __syncthreads();
    }
    if (i < NN) g_rowstart[i] = sh[threadIdx.x] - v;
    if (threadIdx.x == 1023) g_bsums[blockIdx.x] = sh[1023];
}

// scanC with inlined cross-block offset: each block reduces bsums[0..blockIdx).
__global__ void scanC_kernel(int nblocks) {
    __shared__ int sh[64];
    __shared__ int s_off;
    int t = threadIdx.x;
    if (t < 64) sh[t] = (t < blockIdx.x && t < nblocks) ? g_bsums[t] : 0;
    __syncthreads();
    if (t < 32) {
        int v = sh[t] + sh[t + 32];
#pragma unroll
        for (int o = 16; o; o >>= 1) v += __shfl_xor_sync(0xffffffffu, v, o);
        if (t == 0) s_off = v;
    }
    __syncthreads();
    int off = s_off;
    int i = blockIdx.x * 1024 + t;
    if (i < NN) {
        int r = g_rowstart[i] + off;
        g_rowstart[i] = r;
        g_cursor[i]   = r;
    }
    if (i == 0) g_rowstart[NN] = ETOT;
}

__global__ void scatter_kernel(const int* __restrict__ ei) {
    int i = blockIdx.x * blockDim.x + threadIdx.x;
    if (i >= ETOT) return;
    int s, d;
    if (i < EE) {
        if (g_is64) {
            s = (int)((const long long*)ei)[i];
            d = (int)((const long long*)ei)[EE + i];
        } else {
            s = ei[i];
            d = ei[EE + i];
        }
    } else {
        s = d = i - EE;
    }
    int p = atomicAdd(&g_cursor[d], 1);
    g_esrc[p] = s;
}

// ===== B pre-pack: transpose to [n][k], split fp32 -> bf16 hi + lo ======
__global__ void packB_kernel(const float* __restrict__ B1, int NC1,
                             const float* __restrict__ B2, int NC2,
                             int Ktot, int NPad, int offset) {
    int total = NPad * Ktot;
    int Ntot = NC1 + NC2;
    for (int idx = blockIdx.x * blockDim.x + threadIdx.x; idx < total;
         idx += gridDim.x * blockDim.x) {
        int n = idx / Ktot;
        int k = idx - n * Ktot;
        float v = 0.f;
        if (n < NC1)       v = B1[(size_t)k * NC1 + n];
        else if (n < Ntot) v = B2[(size_t)k * NC2 + (n - NC1)];
        __nv_bfloat16 h = __float2bfloat16(v);
        g_bhi[offset + idx] = h;
        g_blo[offset + idx] = __float2bfloat16(v - __bfloat162float(h));
    }
}

// ===== A pre-split: fp32 [NN,K] -> bf16 hi/lo planes [MPAD,K] ===========
__global__ void convA_kernel(const float* __restrict__ X,
                             __nv_bfloat16* __restrict__ hi,
                             __nv_bfloat16* __restrict__ lo, int K) {
    int q = K >> 2;
    int total = MPAD * q;
    for (int idx = blockIdx.x * blockDim.x + threadIdx.x; idx < total;
         idx += gridDim.x * blockDim.x) {
        int r = idx / q;
        int c4 = idx - r * q;
        float4 v = (r < NN) ? ((const float4*)(X + (size_t)r * K))[c4]
                            : make_float4(0.f, 0.f, 0.f, 0.f);
        union { __nv_bfloat162 h[2]; uint2 u; } ph, pl;
        __nv_bfloat16 h0 = __float2bfloat16(v.x), h1 = __float2bfloat16(v.y);
        __nv_bfloat16 h2 = __float2bfloat16(v.z), h3 = __float2bfloat16(v.w);
        ph.h[0].x = h0; ph.h[0].y = h1; ph.h[1].x = h2; ph.h[1].y = h3;
        pl.h[0].x = __float2bfloat16(v.x - __bfloat162float(h0));
        pl.h[0].y = __float2bfloat16(v.y - __bfloat162float(h1));
        pl.h[1].x = __float2bfloat16(v.z - __bfloat162float(h2));
        pl.h[1].y = __float2bfloat16(v.w - __bfloat162float(h3));
        *(uint2*)(hi + (size_t)r * K + c4 * 4) = ph.u;
        *(uint2*)(lo + (size_t)r * K + c4 * 4) = pl.u;
    }
}

// ===== HMMA dual GEMM + fused attention-score epilogue (R10-exact) ======
#define ASTRIDE 40
#define PLB (128 * ASTRIDE * 2)   // bytes per plane buffer (10240)
__global__ void __launch_bounds__(256, 2)
mma_dual_kernel(const __nv_bfloat16* __restrict__ Ahi,
                const __nv_bfloat16* __restrict__ Alo, int Ktot,
                const __nv_bfloat16* __restrict__ Bhi,
                const __nv_bfloat16* __restrict__ Blo,
                int NC1, __half* __restrict__ C1h,
                int NC2, const float* __restrict__ bias2, float* __restrict__ C2,
                const float* __restrict__ attSrc, const float* __restrict__ attDst,
                float* __restrict__ aSrcOut, float* __restrict__ aDstOut, int nheads)
{
    extern __shared__ __nv_bfloat16 sm[];
    int tid = threadIdx.x;
    int wid = tid >> 5, lane = tid & 31;
    int m0 = blockIdx.x * 128;
    int n0 = blockIdx.y * 128;
    int Ntot = NC1 + NC2;
    int wm = (wid >> 1) * 32;
    int wn = (wid & 1) * 64;
    uint32_t smb = smem_u32(sm);

    int crow  = tid >> 1;
    int cpair = (tid & 1) * 2;
    const __nv_bfloat16* aH = Ahi + (size_t)(m0 + crow) * Ktot + cpair * 8;
    const __nv_bfloat16* aL = Alo + (size_t)(m0 + crow) * Ktot + cpair * 8;
    const __nv_bfloat16* bH = Bhi + (size_t)(n0 + crow) * Ktot + cpair * 8;
    const __nv_bfloat16* bL = Blo + (size_t)(n0 + crow) * Ktot + cpair * 8;
    uint32_t dstB = smb + (uint32_t)(crow * ASTRIDE + cpair * 8) * 2;

    int nK = Ktot >> 5;

    float acc[2][8][4];
#pragma unroll
    for (int i = 0; i < 2; i++)
#pragma unroll
        for (int j = 0; j < 8; j++)
#pragma unroll
            for (int q = 0; q < 4; q++) acc[i][j][q] = 0.f;

    uint32_t aoffb = (uint32_t)((lane & 15) * ASTRIDE + (lane >> 4) * 8) * 2;
    uint32_t boffb = (uint32_t)((lane & 7) * ASTRIDE + (lane >> 3) * 8) * 2;

#define ISSUE(kt) do { \
    int _st = (kt) & 1; int _ko = (kt) * 32; \
    uint32_t _sb = dstB + (uint32_t)(_st * 4 * PLB); \
    cp16(_sb,                aH + _ko); cp16(_sb + 16,           aH + _ko + 8); \
    cp16(_sb + PLB,          aL + _ko); cp16(_sb + PLB + 16,     aL + _ko + 8); \
    cp16(_sb + 2 * PLB,      bH + _ko); cp16(_sb + 2 * PLB + 16, bH + _ko + 8); \
    cp16(_sb + 3 * PLB,      bL + _ko); cp16(_sb + 3 * PLB + 16, bL + _ko + 8); \
} while (0)

    ISSUE(0);
    CP_COMMIT();
    if (nK > 1) ISSUE(1);
    CP_COMMIT();

    for (int kt = 0; kt < nK; kt++) {
        CP_WAIT1();
        __syncthreads();
        uint32_t base = smb + (uint32_t)((kt & 1) * 4 * PLB);
        uint32_t sAH = base, sAL = base + PLB, sBH = base + 2 * PLB, sBL = base + 3 * PLB;

#pragma unroll
        for (int kk = 0; kk < 32; kk += 16) {
            uint32_t aHf[2][4], aLf[2][4];
            uint32_t kb = (uint32_t)kk * 2;
#pragma unroll
            for (int mt = 0; mt < 2; mt++) {
                uint32_t ao = (uint32_t)((wm + mt * 16) * ASTRIDE) * 2 + aoffb + kb;
                ldsm_x4(aHf[mt], sAH + ao);
                ldsm_x4(aLf[mt], sAL + ao);
            }
#pragma unroll
            for (int nt = 0; nt < 8; nt++) {
                uint32_t bo = (uint32_t)((wn + nt * 8) * ASTRIDE) * 2 + boffb + kb;
                uint32_t bHf[2], bLf[2];
                ldsm_x2(bHf, sBH + bo);
                ldsm_x2(bLf, sBL + bo);
#pragma unroll
                for (int mt = 0; mt < 2; mt++) {
                    mma16816(acc[mt][nt], aHf[mt], bHf);
                    mma16816(acc[mt][nt], aHf[mt], bLf);
                    mma16816(acc[mt][nt], aLf[mt], bHf);
                }
            }
        }
        __syncthreads();
        if (kt + 2 < nK) ISSUE(kt + 2);
        CP_COMMIT();
    }

    // ---- epilogue: fp16 C1 emit + fp32 C2 emit + fused attn scores ----
    int rbase = m0 + wm + (lane >> 2);
    int cbase = n0 + wn + (lane & 3) * 2;
    bool warpAttn = (n0 + wn) < NC1;
    int hIdx = (n0 + wn) >> 6;
#pragma unroll
    for (int mt = 0; mt < 2; mt++) {
#pragma unroll
        for (int half2 = 0; half2 < 2; half2++) {
            int r = rbase + mt * 16 + half2 * 8;
            float vs = 0.f, vd = 0.f;
#pragma unroll
            for (int nt = 0; nt < 8; nt++) {
                int c = cbase + nt * 8;
                float v0 = acc[mt][nt][half2 * 2 + 0];
                float v1 = acc[mt][nt][half2 * 2 + 1];
                if (r < NN) {
                    if (c < NC1) {
                        *(__half2*)(C1h + (size_t)r * NC1 + c) = __floats2half2_rn(v0, v1);
                    } else if (c < Ntot) {
                        int cc = c - NC1;
                        float2 o; o.x = v0 + bias2[cc]; o.y = v1 + bias2[cc + 1];
                        *(float2*)(C2 + (size_t)r * NC2 + cc) = o;
                    }
                }
                if (warpAttn && c < NC1) {
                    vs += v0 * attSrc[c] + v1 * attSrc[c + 1];
                    vd += v0 * attDst[c] + v1 * attDst[c + 1];
                }
            }
            if (warpAttn) {
                vs += __shfl_xor_sync(0xffffffffu, vs, 1);
                vs += __shfl_xor_sync(0xffffffffu, vs, 2);
                vd += __shfl_xor_sync(0xffffffffu, vd, 1);
                vd += __shfl_xor_sync(0xffffffffu, vd, 2);
                if ((lane & 3) == 0 && r < NN) {
                    aSrcOut[r * nheads + hIdx] = vs;
                    aDstOut[r * nheads + hIdx] = vd;
                }
            }
        }
    }
}

// ---------------- layer-0 softmax-aggregate (warp per node, 1 pass) -----
__global__ void __launch_bounds__(256)
agg0_kernel(const float* __restrict__ b0) {
    int gw = (blockIdx.x * blockDim.x + threadIdx.x) >> 5;
    int lane = threadIdx.x & 31;
    if (gw >= MPAD) return;
    int n = gw;
    if (n >= NN) {   // pad rows: zero the GEMM operand planes
        uint4 z = make_uint4(0u, 0u, 0u, 0u);
        *(uint4*)(g_a1hi + (size_t)n * 256 + lane * 8) = z;
        *(uint4*)(g_a1lo + (size_t)n * 256 + lane * 8) = z;
        return;
    }
    int beg = __ldg(&g_rowstart[n]), end = __ldg(&g_rowstart[n + 1]);
    int h = lane >> 3;
    float adh = __ldg(&g_adst0[n * 4 + h]);

    float den = 0.f;
    float acc[8];
#pragma unroll
    for (int i = 0; i < 8; i++) acc[i] = 0.f;
    const __half* xlb = g_xl0h + lane * 8;
#pragma unroll 4
    for (int j = beg; j < end; j++) {
        int s = __ldg(&g_esrc[j]);
        float e = __ldg(&g_asrc0[s * 4 + h]) + adh;
        e = e > 0.f ? e : NEG * e;
        float w = __expf(e);
        den += w;
        uint4 q = *(const uint4*)(xlb + (size_t)s * 256);
        __half2 p0 = *(__half2*)&q.x, p1 = *(__half2*)&q.y;
        __half2 p2 = *(__half2*)&q.z, p3 = *(__half2*)&q.w;
        float2 f0 = __half22float2(p0), f1 = __half22float2(p1);
        float2 f2 = __half22float2(p2), f3 = __half22float2(p3);
        acc[0] += w * f0.x; acc[1] += w * f0.y;
        acc[2] += w * f1.x; acc[3] += w * f1.y;
        acc[4] += w * f2.x; acc[5] += w * f2.y;
        acc[6] += w * f3.x; acc[7] += w * f3.y;
    }
    float invd = 1.f / (den + 1e-16f);

    // epilogue: normalize, + b0 + xr0, elu, emit bf16 hi/lo planes
    const float4* bq = (const float4*)(b0 + lane * 8);
    const float4* xr = (const float4*)(g_xr0 + (size_t)n * 256 + lane * 8);
    float4 b4a = bq[0], b4b = bq[1];
    float4 xa = xr[0], xb = xr[1];
    float o[8];
    o[0] = acc[0] * invd + b4a.x + xa.x; o[1] = acc[1] * invd + b4a.y + xa.y;
    o[2] = acc[2] * invd + b4a.z + xa.z; o[3] = acc[3] * invd + b4a.w + xa.w;
    o[4] = acc[4] * invd + b4b.x + xb.x; o[5] = acc[5] * invd + b4b.y + xb.y;
    o[6] = acc[6] * invd + b4b.z + xb.z; o[7] = acc[7] * invd + b4b.w + xb.w;
#pragma unroll
    for (int i = 0; i < 8; i++) o[i] = o[i] > 0.f ? o[i] : expm1f(o[i]);
    union { __nv_bfloat162 h[4]; uint4 u; } ph, pl;
#pragma unroll
    for (int i = 0; i < 4; i++) {
        __nv_bfloat16 h0 = __float2bfloat16(o[i * 2]);
        __nv_bfloat16 h1 = __float2bfloat16(o[i * 2 + 1]);
        ph.h[i].x = h0; ph.h[i].y = h1;
        pl.h[i].x = __float2bfloat16(o[i * 2]     - __bfloat162float(h0));
        pl.h[i].y = __float2bfloat16(o[i * 2 + 1] - __bfloat162float(h1));
    }
    *(uint4*)(g_a1hi + (size_t)n * 256 + lane * 8) = ph.u;
    *(uint4*)(g_a1lo + (size_t)n * 256 + lane * 8) = pl.u;
}

// ---------------- layer-1 softmax-aggregate (warp per node, 1 pass) -----
__global__ void agg1_kernel(const float* __restrict__ b1, float* __restrict__ out) {
    int gw = (blockIdx.x * blockDim.x + threadIdx.x) >> 5;
    int lane = threadIdx.x & 31;
    if (gw >= NN) return;
    int n = gw;
    int beg = __ldg(&g_rowstart[n]), end = __ldg(&g_rowstart[n + 1]);
    float ad = g_adst1[n];

    float sum = 0.f, acc0 = 0.f, acc1 = 0.f;
#pragma unroll 4
    for (int j = beg; j < end; j++) {
        int s = __ldg(&g_esrc[j]);
        float e = __ldg(&g_asrc1[s]) + ad;
        e = e > 0.f ? e : NEG * e;
        float w = __expf(e);
        sum += w;
        acc0 += w * __half2float(g_xl1h[(size_t)s * OUTC + lane]);
        if (lane < 8) acc1 += w * __half2float(g_xl1h[(size_t)s * OUTC + 32 + lane]);
    }
    float invd = 1.f / (sum + 1e-16f);

    float v0 = acc0 * invd + b1[lane] + g_xr1[(size_t)n * OUTC + lane];
    out[(size_t)n * OUTC + lane] = v0 > 0.f ? v0 : expm1f(v0);
    if (lane < 8) {
        float v1 = acc1 * invd + b1[32 + lane] + g_xr1[(size_t)n * OUTC + 32 + lane];
        out[(size_t)n * OUTC + 32 + lane] = v1 > 0.f ? v1 : expm1f(v1);
    }
}

// ------------------------------ launch -----------------------------------
extern "C" void kernel_launch(void* const* d_in, const int* in_sizes, int n_in,
                              void* d_out, int out_size) {
    const float* x        = (const float*)d_in[0];
    const int*   ei       = (const int*)  d_in[1];
    const float* W0       = (const float*)d_in[2];
    const float* b0       = (const float*)d_in[3];
    const float* att_src0 = (const float*)d_in[4];
    const float* att_dst0 = (const float*)d_in[5];
    const float* Wr0      = (const float*)d_in[6];
    const float* br0      = (const float*)d_in[7];
    const float* W1       = (const float*)d_in[8];
    const float* b1       = (const float*)d_in[9];
    const float* att_src1 = (const float*)d_in[10];
    const float* att_dst1 = (const float*)d_in[11];
    const float* Wr1      = (const float*)d_in[12];
    const float* br1      = (const float*)d_in[13];
    float* out = (float*)d_out;

    float *xr0, *xr1, *as0, *ad0, *as1, *ad1;
    __half *xl0h, *xl1h;
    __nv_bfloat16 *a0hi, *a0lo, *a1hi, *a1lo, *bhi, *blo;
    cudaGetSymbolAddress((void**)&xr0, g_xr0);
    cudaGetSymbolAddress((void**)&xr1, g_xr1);
    cudaGetSymbolAddress((void**)&xl0h, g_xl0h);
    cudaGetSymbolAddress((void**)&xl1h, g_xl1h);
    cudaGetSymbolAddress((void**)&as0, g_asrc0);
    cudaGetSymbolAddress((void**)&ad0, g_adst0);
    cudaGetSymbolAddress((void**)&as1, g_asrc1);
    cudaGetSymbolAddress((void**)&ad1, g_adst1);
    cudaGetSymbolAddress((void**)&a0hi, g_a0hi);
    cudaGetSymbolAddress((void**)&a0lo, g_a0lo);
    cudaGetSymbolAddress((void**)&a1hi, g_a1hi);
    cudaGetSymbolAddress((void**)&a1lo, g_a1lo);
    cudaGetSymbolAddress((void**)&bhi, g_bhi);
    cudaGetSymbolAddress((void**)&blo, g_blo);

    cudaFuncSetAttribute(mma_dual_kernel,
                         cudaFuncAttributeMaxDynamicSharedMemorySize, 8 * PLB);

    const int scanBlocks = (NN + 1023) / 1024;   // 49
    const int mTiles = MPAD / 128;               // 391

    // ---- fork ----
    cudaEventRecord(g_ss.evFork, 0);
    cudaStreamWaitEvent(g_ss.s2, g_ss.evFork, 0);

    // side stream: B pre-pack first (mma0 waits on it), then CSR build
    packB_kernel<<<128, 256, 0, g_ss.s2>>>(W0, 256, Wr0, 256, FIN, 512, 0);
    packB_kernel<<<64, 256, 0, g_ss.s2>>>(W1, OUTC, Wr1, OUTC, HID, 128, 65536);
    cudaEventRecord(g_ss.evPack, g_ss.s2);
    zero_detect_kernel<<<(NN + 255) / 256, 256, 0, g_ss.s2>>>(ei);
    hist_kernel<<<(EE + 255) / 256, 256, 0, g_ss.s2>>>(ei);
    scanA_kernel<<<scanBlocks, 1024, 0, g_ss.s2>>>();
    scanC_kernel<<<scanBlocks, 1024, 0, g_ss.s2>>>(scanBlocks);
    scatter_kernel<<<(ETOT + 255) / 256, 256, 0, g_ss.s2>>>(ei);
    cudaEventRecord(g_ss.evJoin, g_ss.s2);

    // main stream: A convert -> layer-0 GEMM (+fused attn0)
    convA_kernel<<<256, 256>>>(x, a0hi, a0lo, FIN);
    cudaStreamWaitEvent(0, g_ss.evPack, 0);
    mma_dual_kernel<<<dim3(mTiles, 4), 256, 8 * PLB>>>(
        a0hi, a0lo, FIN, bhi, blo, 256, xl0h, 256, br0, xr0,
        att_src0, att_dst0, as0, ad0, 4);

    // join: agg0 needs CSR + layer-0 outputs
    cudaStreamWaitEvent(0, g_ss.evJoin, 0);
    agg0_kernel<<<(MPAD * 32 + 255) / 256, 256>>>(b0);

    // layer 1 GEMM (+fused attn1) and final aggregate
    mma_dual_kernel<<<dim3(mTiles, 1), 256, 8 * PLB>>>(
        a1hi, a1lo, HID, bhi + 65536, blo + 65536, OUTC, xl1h, OUTC, br1, xr1,
        att_src1, att_dst1, as1, ad1, 1);
    agg1_kernel<<<(NN * 32 + 255) / 256, 256>>>(b1, out);
}

// round 16
// speedup vs baseline: 1.5376x; 1.5376x over previous
#include <cuda_runtime.h>
#include <cuda_bf16.h>
#include <cuda_fp16.h>
#include <cstdint>

#define NN   50000
#define EE   800000
#define ETOT 850000   // EE + NN self loops
#define MPAD 50048    // 391 * 128
#define FIN  128
#define HID  256
#define OUTC 40
#define NEG  0.2f

// ---------------- device scratch (no cudaMalloc allowed) ----------------
__device__ __align__(16) float g_xr0[(size_t)NN * 256];
__device__ __align__(16) __half g_xl0h[(size_t)NN * 256];   // fp16 xl0 (GEMM epilogue emit)
__device__ __align__(16) float g_asrc0[NN * 4];
__device__ __align__(16) float g_adst0[NN * 4];
__device__ __align__(16) float g_xr1[(size_t)NN * OUTC];
__device__ __align__(16) __half g_xl1h[(size_t)NN * OUTC];
__device__ float g_asrc1[NN];
__device__ float g_adst1[NN];
__device__ int   g_deg[NN];
__device__ int   g_rowstart[NN + 1];
__device__ int   g_cursor[NN];
__device__ int   g_esrc[ETOT];
__device__ int   g_bsums[64];
__device__ int   g_is64;
// pre-split bf16 operand planes (padded, guard-free GEMM loads)
__device__ __align__(16) __nv_bfloat16 g_a0hi[(size_t)MPAD * FIN];
__device__ __align__(16) __nv_bfloat16 g_a0lo[(size_t)MPAD * FIN];
__device__ __align__(16) __nv_bfloat16 g_a1hi[(size_t)MPAD * HID];
__device__ __align__(16) __nv_bfloat16 g_a1lo[(size_t)MPAD * HID];
__device__ __align__(16) __nv_bfloat16 g_bhi[98304];
__device__ __align__(16) __nv_bfloat16 g_blo[98304];

// ---- side stream + events for fork/join inside graph capture -----------
struct SideStream {
    cudaStream_t s2;
    cudaEvent_t evFork, evPack, evJoin;
    SideStream() {
        cudaStreamCreateWithFlags(&s2, cudaStreamNonBlocking);
        cudaEventCreateWithFlags(&evFork, cudaEventDisableTiming);
        cudaEventCreateWithFlags(&evPack, cudaEventDisableTiming);
        cudaEventCreateWithFlags(&evJoin, cudaEventDisableTiming);
    }
};
static SideStream g_ss;

// ======================= PTX helpers ====================================
__device__ __forceinline__ uint32_t smem_u32(const void* p) {
    uint32_t a;
    asm("{ .reg .u64 t; cvta.to.shared.u64 t, %1; cvt.u32.u64 %0, t; }" : "=r"(a) : "l"(p));
    return a;
}
__device__ __forceinline__ void ldsm_x4(uint32_t* r, uint32_t addr) {
    asm volatile("ldmatrix.sync.aligned.m8n8.x4.shared.b16 {%0,%1,%2,%3}, [%4];"
        : "=r"(r[0]), "=r"(r[1]), "=r"(r[2]), "=r"(r[3]) : "r"(addr));
}
__device__ __forceinline__ void ldsm_x2(uint32_t* r, uint32_t addr) {
    asm volatile("ldmatrix.sync.aligned.m8n8.x2.shared.b16 {%0,%1}, [%2];"
        : "=r"(r[0]), "=r"(r[1]) : "r"(addr));
}
__device__ __forceinline__ void mma16816(float* d, const uint32_t* a, const uint32_t* b) {
    asm volatile("mma.sync.aligned.m16n8k16.row.col.f32.bf16.bf16.f32 "
        "{%0,%1,%2,%3}, {%4,%5,%6,%7}, {%8,%9}, {%0,%1,%2,%3};"
        : "+f"(d[0]), "+f"(d[1]), "+f"(d[2]), "+f"(d[3])
        : "r"(a[0]), "r"(a[1]), "r"(a[2]), "r"(a[3]), "r"(b[0]), "r"(b[1]));
}
__device__ __forceinline__ void cp16(uint32_t dst, const void* src) {
    asm volatile("cp.async.cg.shared.global [%0], [%1], 16;" :: "r"(dst), "l"(src));
}
#define CP_COMMIT() asm volatile("cp.async.commit_group;")
#define CP_WAIT1()  asm volatile("cp.async.wait_group 1;")

// ------------- zero degrees + dtype detect (merged, side chain) ---------
__global__ void zero_detect_kernel(const int* __restrict__ ei) {
    int i = blockIdx.x * blockDim.x + threadIdx.x;
    if (i < NN) g_deg[i] = 0;
    if (blockIdx.x == 0 && threadIdx.x < 32) {
        int lane = threadIdx.x;
        int nz = 0;
        for (int k = lane * 2 + 1; k < 256; k += 64) nz += (ei[k] != 0);
        unsigned m = __ballot_sync(0xffffffffu, nz != 0);
        if (lane == 0) g_is64 = (m == 0u) ? 1 : 0;
    }
}

__global__ void hist_kernel(const int* __restrict__ ei) {
    int e = blockIdx.x * blockDim.x + threadIdx.x;
    if (e >= EE) return;
    int d;
    if (g_is64) d = (int)((const long long*)ei)[EE + e];
    else        d = ei[EE + e];
    atomicAdd(&g_deg[d], 1);
}

__global__ void scanA_kernel() {
    __shared__ int sh[1024];
    int i = blockIdx.x * 1024 + threadIdx.x;
    int v = (i < NN) ? (g_deg[i] + 1) : 0;
    sh[threadIdx.x] = v;
    __syncthreads();
    for (int off = 1; off < 1024; off <<= 1) {
        int t = (threadIdx.x >= off) ? sh[threadIdx.x - off] : 0;
        __syncthreads();
        sh[threadIdx.x] += t;
        __syncthreads();
    }
    if (i < NN) g_rowstart[i] = sh[threadIdx.x] - v;
    if (threadIdx.x == 1023) g_bsums[blockIdx.x] = sh[1023];
}

// scanC with inlined cross-block offset: each block reduces bsums[0..blockIdx).
__global__ void scanC_kernel(int nblocks) {
    __shared__ int sh[64];
    __shared__ int s_off;
    int t = threadIdx.x;
    if (t < 64) sh[t] = (t < blockIdx.x && t < nblocks) ? g_bsums[t] : 0;
    __syncthreads();
    if (t < 32) {
        int v = sh[t] + sh[t + 32];
#pragma unroll
        for (int o = 16; o; o >>= 1) v += __shfl_xor_sync(0xffffffffu, v, o);
        if (t == 0) s_off = v;
    }
    __syncthreads();
    int off = s_off;
    int i = blockIdx.x * 1024 + t;
    if (i < NN) {
        int r = g_rowstart[i] + off;
        g_rowstart[i] = r;
        g_cursor[i]   = r;
    }
    if (i == 0) g_rowstart[NN] = ETOT;
}

__global__ void scatter_kernel(const int* __restrict__ ei) {
    int i = blockIdx.x * blockDim.x + threadIdx.x;
    if (i >= ETOT) return;
    int s, d;
    if (i < EE) {
        if (g_is64) {
            s = (int)((const long long*)ei)[i];
            d = (int)((const long long*)ei)[EE + i];
        } else {
            s = ei[i];
            d = ei[EE + i];
        }
    } else {
        s = d = i - EE;
    }
    int p = atomicAdd(&g_cursor[d], 1);
    g_esrc[p] = s;
}

// ===== B pre-pack: transpose to [n][k], split fp32 -> bf16 hi + lo ======
__global__ void packB_kernel(const float* __restrict__ B1, int NC1,
                             const float* __restrict__ B2, int NC2,
                             int Ktot, int NPad, int offset) {
    int total = NPad * Ktot;
    int Ntot = NC1 + NC2;
    for (int idx = blockIdx.x * blockDim.x + threadIdx.x; idx < total;
         idx += gridDim.x * blockDim.x) {
        int n = idx / Ktot;
        int k = idx - n * Ktot;
        float v = 0.f;
        if (n < NC1)       v = B1[(size_t)k * NC1 + n];
        else if (n < Ntot) v = B2[(size_t)k * NC2 + (n - NC1)];
        __nv_bfloat16 h = __float2bfloat16(v);
        g_bhi[offset + idx] = h;
        g_blo[offset + idx] = __float2bfloat16(v - __bfloat162float(h));
    }
}

// ===== A pre-split: fp32 [NN,K] -> bf16 hi/lo planes [MPAD,K] ===========
__global__ void convA_kernel(const float* __restrict__ X,
                             __nv_bfloat16* __restrict__ hi,
                             __nv_bfloat16* __restrict__ lo, int K) {
    int q = K >> 2;
    int total = MPAD * q;
    for (int idx = blockIdx.x * blockDim.x + threadIdx.x; idx < total;
         idx += gridDim.x * blockDim.x) {
        int r = idx / q;
        int c4 = idx - r * q;
        float4 v = (r < NN) ? ((const float4*)(X + (size_t)r * K))[c4]
                            : make_float4(0.f, 0.f, 0.f, 0.f);
        union { __nv_bfloat162 h[2]; uint2 u; } ph, pl;
        __nv_bfloat16 h0 = __float2bfloat16(v.x), h1 = __float2bfloat16(v.y);
        __nv_bfloat16 h2 = __float2bfloat16(v.z), h3 = __float2bfloat16(v.w);
        ph.h[0].x = h0; ph.h[0].y = h1; ph.h[1].x = h2; ph.h[1].y = h3;
        pl.h[0].x = __float2bfloat16(v.x - __bfloat162float(h0));
        pl.h[0].y = __float2bfloat16(v.y - __bfloat162float(h1));
        pl.h[1].x = __float2bfloat16(v.z - __bfloat162float(h2));
        pl.h[1].y = __float2bfloat16(v.w - __bfloat162float(h3));
        *(uint2*)(hi + (size_t)r * K + c4 * 4) = ph.u;
        *(uint2*)(lo + (size_t)r * K + c4 * 4) = pl.u;
    }
}

// ===== HMMA dual GEMM + fused attention-score epilogue (R10-exact) ======
#define ASTRIDE 40
#define PLB (128 * ASTRIDE * 2)   // bytes per plane buffer (10240)
__global__ void __launch_bounds__(256, 2)
mma_dual_kernel(const __nv_bfloat16* __restrict__ Ahi,
                const __nv_bfloat16* __restrict__ Alo, int Ktot,
                const __nv_bfloat16* __restrict__ Bhi,
                const __nv_bfloat16* __restrict__ Blo,
                int NC1, __half* __restrict__ C1h,
                int NC2, const float* __restrict__ bias2, float* __restrict__ C2,
                const float* __restrict__ attSrc, const float* __restrict__ attDst,
                float* __restrict__ aSrcOut, float* __restrict__ aDstOut, int nheads)
{
    extern __shared__ __nv_bfloat16 sm[];
    int tid = threadIdx.x;
    int wid = tid >> 5, lane = tid & 31;
    int m0 = blockIdx.x * 128;
    int n0 = blockIdx.y * 128;
    int Ntot = NC1 + NC2;
    int wm = (wid >> 1) * 32;
    int wn = (wid & 1) * 64;
    uint32_t smb = smem_u32(sm);

    int crow  = tid >> 1;
    int cpair = (tid & 1) * 2;
    const __nv_bfloat16* aH = Ahi + (size_t)(m0 + crow) * Ktot + cpair * 8;
    const __nv_bfloat16* aL = Alo + (size_t)(m0 + crow) * Ktot + cpair * 8;
    const __nv_bfloat16* bH = Bhi + (size_t)(n0 + crow) * Ktot + cpair * 8;
    const __nv_bfloat16* bL = Blo + (size_t)(n0 + crow) * Ktot + cpair * 8;
    uint32_t dstB = smb + (uint32_t)(crow * ASTRIDE + cpair * 8) * 2;

    int nK = Ktot >> 5;

    float acc[2][8][4];
#pragma unroll
    for (int i = 0; i < 2; i++)
#pragma unroll
        for (int j = 0; j < 8; j++)
#pragma unroll
            for (int q = 0; q < 4; q++) acc[i][j][q] = 0.f;

    uint32_t aoffb = (uint32_t)((lane & 15) * ASTRIDE + (lane >> 4) * 8) * 2;
    uint32_t boffb = (uint32_t)((lane & 7) * ASTRIDE + (lane >> 3) * 8) * 2;

#define ISSUE(kt) do { \
    int _st = (kt) & 1; int _ko = (kt) * 32; \
    uint32_t _sb = dstB + (uint32_t)(_st * 4 * PLB); \
    cp16(_sb,                aH + _ko); cp16(_sb + 16,           aH + _ko + 8); \
    cp16(_sb + PLB,          aL + _ko); cp16(_sb + PLB + 16,     aL + _ko + 8); \
    cp16(_sb + 2 * PLB,      bH + _ko); cp16(_sb + 2 * PLB + 16, bH + _ko + 8); \
    cp16(_sb + 3 * PLB,      bL + _ko); cp16(_sb + 3 * PLB + 16, bL + _ko + 8); \
} while (0)

    ISSUE(0);
    CP_COMMIT();
    if (nK > 1) ISSUE(1);
    CP_COMMIT();

    for (int kt = 0; kt < nK; kt++) {
        CP_WAIT1();
        __syncthreads();
        uint32_t base = smb + (uint32_t)((kt & 1) * 4 * PLB);
        uint32_t sAH = base, sAL = base + PLB, sBH = base + 2 * PLB, sBL = base + 3 * PLB;

#pragma unroll
        for (int kk = 0; kk < 32; kk += 16) {
            uint32_t aHf[2][4], aLf[2][4];
            uint32_t kb = (uint32_t)kk * 2;
#pragma unroll
            for (int mt = 0; mt < 2; mt++) {
                uint32_t ao = (uint32_t)((wm + mt * 16) * ASTRIDE) * 2 + aoffb + kb;
                ldsm_x4(aHf[mt], sAH + ao);
                ldsm_x4(aLf[mt], sAL + ao);
            }
#pragma unroll
            for (int nt = 0; nt < 8; nt++) {
                uint32_t bo = (uint32_t)((wn + nt * 8) * ASTRIDE) * 2 + boffb + kb;
                uint32_t bHf[2], bLf[2];
                ldsm_x2(bHf, sBH + bo);
                ldsm_x2(bLf, sBL + bo);
#pragma unroll
                for (int mt = 0; mt < 2; mt++) {
                    mma16816(acc[mt][nt], aHf[mt], bHf);
                    mma16816(acc[mt][nt], aHf[mt], bLf);
                    mma16816(acc[mt][nt], aLf[mt], bHf);
                }
            }
        }
        __syncthreads();
        if (kt + 2 < nK) ISSUE(kt + 2);
        CP_COMMIT();
    }

    // ---- epilogue: fp16 C1 emit + fp32 C2 emit + fused attn scores ----
    int rbase = m0 + wm + (lane >> 2);
    int cbase = n0 + wn + (lane & 3) * 2;
    bool warpAttn = (n0 + wn) < NC1;
    int hIdx = (n0 + wn) >> 6;
#pragma unroll
    for (int mt = 0; mt < 2; mt++) {
#pragma unroll
        for (int half2 = 0; half2 < 2; half2++) {
            int r = rbase + mt * 16 + half2 * 8;
            float vs = 0.f, vd = 0.f;
#pragma unroll
            for (int nt = 0; nt < 8; nt++) {
                int c = cbase + nt * 8;
                float v0 = acc[mt][nt][half2 * 2 + 0];
                float v1 = acc[mt][nt][half2 * 2 + 1];
                if (r < NN) {
                    if (c < NC1) {
                        *(__half2*)(C1h + (size_t)r * NC1 + c) = __floats2half2_rn(v0, v1);
                    } else if (c < Ntot) {
                        int cc = c - NC1;
                        float2 o; o.x = v0 + bias2[cc]; o.y = v1 + bias2[cc + 1];
                        *(float2*)(C2 + (size_t)r * NC2 + cc) = o;
                    }
                }
                if (warpAttn && c < NC1) {
                    vs += v0 * attSrc[c] + v1 * attSrc[c + 1];
                    vd += v0 * attDst[c] + v1 * attDst[c + 1];
                }
            }
            if (warpAttn) {
                vs += __shfl_xor_sync(0xffffffffu, vs, 1);
                vs += __shfl_xor_sync(0xffffffffu, vs, 2);
                vd += __shfl_xor_sync(0xffffffffu, vd, 1);
                vd += __shfl_xor_sync(0xffffffffu, vd, 2);
                if ((lane & 3) == 0 && r < NN) {
                    aSrcOut[r * nheads + hIdx] = vs;
                    aDstOut[r * nheads + hIdx] = vd;
                }
            }
        }
    }
}

// ---------------- layer-0 softmax-aggregate (warp per node, 1 pass) -----
__global__ void __launch_bounds__(256)
agg0_kernel(const float* __restrict__ b0) {
    int gw = (blockIdx.x * blockDim.x + threadIdx.x) >> 5;
    int lane = threadIdx.x & 31;
    if (gw >= MPAD) return;
    int n = gw;
    if (n >= NN) {   // pad rows: zero the GEMM operand planes
        uint4 z = make_uint4(0u, 0u, 0u, 0u);
        *(uint4*)(g_a1hi + (size_t)n * 256 + lane * 8) = z;
        *(uint4*)(g_a1lo + (size_t)n * 256 + lane * 8) = z;
        return;
    }
    int beg = __ldg(&g_rowstart[n]), end = __ldg(&g_rowstart[n + 1]);
    int h = lane >> 3;
    float adh = __ldg(&g_adst0[n * 4 + h]);

    float den = 0.f;
    float acc[8];
#pragma unroll
    for (int i = 0; i < 8; i++) acc[i] = 0.f;
    const __half* xlb = g_xl0h + lane * 8;
#pragma unroll 4
    for (int j = beg; j < end; j++) {
        int s = __ldg(&g_esrc[j]);
        float e = __ldg(&g_asrc0[s * 4 + h]) + adh;
        e = e > 0.f ? e : NEG * e;
        float w = __expf(e);
        den += w;
        uint4 q = *(const uint4*)(xlb + (size_t)s * 256);
        __half2 p0 = *(__half2*)&q.x, p1 = *(__half2*)&q.y;
        __half2 p2 = *(__half2*)&q.z, p3 = *(__half2*)&q.w;
        float2 f0 = __half22float2(p0), f1 = __half22float2(p1);
        float2 f2 = __half22float2(p2), f3 = __half22float2(p3);
        acc[0] += w * f0.x; acc[1] += w * f0.y;
        acc[2] += w * f1.x; acc[3] += w * f1.y;
        acc[4] += w * f2.x; acc[5] += w * f2.y;
        acc[6] += w * f3.x; acc[7] += w * f3.y;
    }
    float invd = 1.f / (den + 1e-16f);

    // epilogue: normalize, + b0 + xr0, elu, emit bf16 hi/lo planes
    const float4* bq = (const float4*)(b0 + lane * 8);
    const float4* xr = (const float4*)(g_xr0 + (size_t)n * 256 + lane * 8);
    float4 b4a = bq[0], b4b = bq[1];
    float4 xa = xr[0], xb = xr[1];
    float o[8];
    o[0] = acc[0] * invd + b4a.x + xa.x; o[1] = acc[1] * invd + b4a.y + xa.y;
    o[2] = acc[2] * invd + b4a.z + xa.z; o[3] = acc[3] * invd + b4a.w + xa.w;
    o[4] = acc[4] * invd + b4b.x + xb.x; o[5] = acc[5] * invd + b4b.y + xb.y;
    o[6] = acc[6] * invd + b4b.z + xb.z; o[7] = acc[7] * invd + b4b.w + xb.w;
#pragma unroll
    for (int i = 0; i < 8; i++) o[i] = o[i] > 0.f ? o[i] : expm1f(o[i]);
    union { __nv_bfloat162 h[4]; uint4 u; } ph, pl;
#pragma unroll
    for (int i = 0; i < 4; i++) {
        __nv_bfloat16 h0 = __float2bfloat16(o[i * 2]);
        __nv_bfloat16 h1 = __float2bfloat16(o[i * 2 + 1]);
        ph.h[i].x = h0; ph.h[i].y = h1;
        pl.h[i].x = __float2bfloat16(o[i * 2]     - __bfloat162float(h0));
        pl.h[i].y = __float2bfloat16(o[i * 2 + 1] - __bfloat162float(h1));
    }
    *(uint4*)(g_a1hi + (size_t)n * 256 + lane * 8) = ph.u;
    *(uint4*)(g_a1lo + (size_t)n * 256 + lane * 8) = pl.u;
}

// ---------------- layer-1 softmax-aggregate (warp per node, 1 pass) -----
__global__ void agg1_kernel(const float* __restrict__ b1, float* __restrict__ out) {
    int gw = (blockIdx.x * blockDim.x + threadIdx.x) >> 5;
    int lane = threadIdx.x & 31;
    if (gw >= NN) return;
    int n = gw;
    int beg = __ldg(&g_rowstart[n]), end = __ldg(&g_rowstart[n + 1]);
    float ad = g_adst1[n];

    float sum = 0.f, acc0 = 0.f, acc1 = 0.f;
#pragma unroll 4
    for (int j = beg; j < end; j++) {
        int s = __ldg(&g_esrc[j]);
        float e = __ldg(&g_asrc1[s]) + ad;
        e = e > 0.f ? e : NEG * e;
        float w = __expf(e);
        sum += w;
        acc0 += w * __half2float(g_xl1h[(size_t)s * OUTC + lane]);
        if (lane < 8) acc1 += w * __half2float(g_xl1h[(size_t)s * OUTC + 32 + lane]);
    }
    float invd = 1.f / (sum + 1e-16f);

    float v0 = acc0 * invd + b1[lane] + g_xr1[(size_t)n * OUTC + lane];
    out[(size_t)n * OUTC + lane] = v0 > 0.f ? v0 : expm1f(v0);
    if (lane < 8) {
        float v1 = acc1 * invd + b1[32 + lane] + g_xr1[(size_t)n * OUTC + 32 + lane];
        out[(size_t)n * OUTC + 32 + lane] = v1 > 0.f ? v1 : expm1f(v1);
    }
}

// ------------------------------ launch -----------------------------------
extern "C" void kernel_launch(void* const* d_in, const int* in_sizes, int n_in,
                              void* d_out, int out_size) {
    const float* x        = (const float*)d_in[0];
    const int*   ei       = (const int*)  d_in[1];
    const float* W0       = (const float*)d_in[2];
    const float* b0       = (const float*)d_in[3];
    const float* att_src0 = (const float*)d_in[4];
    const float* att_dst0 = (const float*)d_in[5];
    const float* Wr0      = (const float*)d_in[6];
    const float* br0      = (const float*)d_in[7];
    const float* W1       = (const float*)d_in[8];
    const float* b1       = (const float*)d_in[9];
    const float* att_src1 = (const float*)d_in[10];
    const float* att_dst1 = (const float*)d_in[11];
    const float* Wr1      = (const float*)d_in[12];
    const float* br1      = (const float*)d_in[13];
    float* out = (float*)d_out;

    float *xr0, *xr1, *as0, *ad0, *as1, *ad1;
    __half *xl0h, *xl1h;
    __nv_bfloat16 *a0hi, *a0lo, *a1hi, *a1lo, *bhi, *blo;
    cudaGetSymbolAddress((void**)&xr0, g_xr0);
    cudaGetSymbolAddress((void**)&xr1, g_xr1);
    cudaGetSymbolAddress((void**)&xl0h, g_xl0h);
    cudaGetSymbolAddress((void**)&xl1h, g_xl1h);
    cudaGetSymbolAddress((void**)&as0, g_asrc0);
    cudaGetSymbolAddress((void**)&ad0, g_adst0);
    cudaGetSymbolAddress((void**)&as1, g_asrc1);
    cudaGetSymbolAddress((void**)&ad1, g_adst1);
    cudaGetSymbolAddress((void**)&a0hi, g_a0hi);
    cudaGetSymbolAddress((void**)&a0lo, g_a0lo);
    cudaGetSymbolAddress((void**)&a1hi, g_a1hi);
    cudaGetSymbolAddress((void**)&a1lo, g_a1lo);
    cudaGetSymbolAddress((void**)&bhi, g_bhi);
    cudaGetSymbolAddress((void**)&blo, g_blo);

    cudaFuncSetAttribute(mma_dual_kernel,
                         cudaFuncAttributeMaxDynamicSharedMemorySize, 8 * PLB);

    const int scanBlocks = (NN + 1023) / 1024;   // 49
    const int mTiles = MPAD / 128;               // 391

    // ---- fork ----
    cudaEventRecord(g_ss.evFork, 0);
    cudaStreamWaitEvent(g_ss.s2, g_ss.evFork, 0);

    // side stream: B pre-pack first (mma0 waits on it), then CSR build
    packB_kernel<<<128, 256, 0, g_ss.s2>>>(W0, 256, Wr0, 256, FIN, 512, 0);
    packB_kernel<<<64, 256, 0, g_ss.s2>>>(W1, OUTC, Wr1, OUTC, HID, 128, 65536);
    cudaEventRecord(g_ss.evPack, g_ss.s2);
    zero_detect_kernel<<<(NN + 255) / 256, 256, 0, g_ss.s2>>>(ei);
    hist_kernel<<<(EE + 255) / 256, 256, 0, g_ss.s2>>>(ei);
    scanA_kernel<<<scanBlocks, 1024, 0, g_ss.s2>>>();
    scanC_kernel<<<scanBlocks, 1024, 0, g_ss.s2>>>(scanBlocks);
    scatter_kernel<<<(ETOT + 255) / 256, 256, 0, g_ss.s2>>>(ei);
    cudaEventRecord(g_ss.evJoin, g_ss.s2);

    // main stream: A convert -> layer-0 GEMM (+fused attn0)
    convA_kernel<<<256, 256>>>(x, a0hi, a0lo, FIN);
    cudaStreamWaitEvent(0, g_ss.evPack, 0);
    mma_dual_kernel<<<dim3(mTiles, 4), 256, 8 * PLB>>>(
        a0hi, a0lo, FIN, bhi, blo, 256, xl0h, 256, br0, xr0,
        att_src0, att_dst0, as0, ad0, 4);

    // join: agg0 needs CSR + layer-0 outputs
    cudaStreamWaitEvent(0, g_ss.evJoin, 0);
    agg0_kernel<<<(MPAD * 32 + 255) / 256, 256>>>(b0);

    // layer 1 GEMM (+fused attn1) and final aggregate
    mma_dual_kernel<<<dim3(mTiles, 1), 256, 8 * PLB>>>(
        a1hi, a1lo, HID, bhi + 65536, blo + 65536, OUTC, xl1h, OUTC, br1, xr1,
        att_src1, att_dst1, as1, ad1, 1);
    agg1_kernel<<<(NN * 32 + 255) / 256, 256>>>(b1, out);
}